// round 1
// baseline (speedup 1.0000x reference)
#include <cuda_runtime.h>
#include <cuda_bf16.h>

// Problem shape (fixed by setup_inputs): x [8, 4096, 1024] f32, angles [32768, 1024] f32.
// out[b,s,d] = x[b,s,d] + pe[s,d] + cos( sum_{i % 8 == d%8} angles[b*4096+s, i] )
//
// One CTA per sequence position s (4096 CTAs, 256 threads):
//   Phase A: compute pe[s, 0..1023] into SMEM (2 sincosf per thread).
//   Phase B: warp w reduces angles row for batch b=w -> theta[8] -> phase[b][8] (cos).
//   Phase D: for each b: out row = x row + pe + phase[b][d%8], float4 everywhere.

static constexpr int Dk = 1024;
static constexpr int Sk = 4096;
static constexpr int Bk = 8;

__global__ __launch_bounds__(256) void peq_kernel(
    const float* __restrict__ x,
    const float* __restrict__ angles,
    float* __restrict__ out)
{
    __shared__ __align__(16) float pe[Dk];
    __shared__ __align__(16) float phase[Bk][8];

    const int t    = threadIdx.x;
    const int s    = blockIdx.x;
    const int warp = t >> 5;
    const int lane = t & 31;

    // ---------------- Phase A: positional encoding for row s ----------------
    // pe[2p]   = sin(s * 10000^(-2p/1024))
    // pe[2p+1] = cos(s * 10000^(-2p/1024)),  pairs p = 0..511; thread t owns p=2t, 2t+1.
    {
        const float cexp = -9.210340371976184f / 1024.0f; // -ln(10000)/1024
        const float fs = (float)s;
        const int p0 = 2 * t;
        const int p1 = 2 * t + 1;
        float sn0, cs0, sn1, cs1;
        sincosf(fs * expf((float)(2 * p0) * cexp), &sn0, &cs0);
        sincosf(fs * expf((float)(2 * p1) * cexp), &sn1, &cs1);
        float4 v; v.x = sn0; v.y = cs0; v.z = sn1; v.w = cs1;
        ((float4*)pe)[t] = v;
    }

    // ---------------- Phase B: per-wire angle reduction, one warp per batch ----------------
    {
        const int b = warp;                       // 8 warps <-> 8 batches
        const float4* arow =
            (const float4*)(angles + ((size_t)b * Sk + s) * Dk);
        // lane loads elements 128k + 4*lane .. +3  -> wires 4*(lane&1) + {0..3}
        float a0 = 0.f, a1 = 0.f, a2 = 0.f, a3 = 0.f;
        #pragma unroll
        for (int k = 0; k < 8; k++) {
            float4 v = arow[k * 32 + lane];
            a0 += v.x; a1 += v.y; a2 += v.z; a3 += v.w;
        }
        // parity-preserving butterfly: combine lanes of equal (lane&1)
        #pragma unroll
        for (int m = 2; m <= 16; m <<= 1) {
            a0 += __shfl_xor_sync(0xffffffffu, a0, m);
            a1 += __shfl_xor_sync(0xffffffffu, a1, m);
            a2 += __shfl_xor_sync(0xffffffffu, a2, m);
            a3 += __shfl_xor_sync(0xffffffffu, a3, m);
        }
        if (lane < 2) {
            const int bw = 4 * lane;              // lane0 -> wires 0..3, lane1 -> wires 4..7
            phase[b][bw + 0] = cosf(a0);
            phase[b][bw + 1] = cosf(a1);
            phase[b][bw + 2] = cosf(a2);
            phase[b][bw + 3] = cosf(a3);
        }
    }

    __syncthreads();

    // ---------------- Phase D: streamed add, 8 rows ----------------
    const float4 pev = ((const float4*)pe)[t];
    const int bw = 4 * (t & 1);                   // wires for elements 4t..4t+3
    #pragma unroll
    for (int b = 0; b < Bk; b++) {
        const float4 ph = *(const float4*)&phase[b][bw];
        const size_t off = ((size_t)b * Sk + s) * Dk;
        float4 xv = ((const float4*)(x + off))[t];
        float4 o;
        o.x = xv.x + pev.x + ph.x;
        o.y = xv.y + pev.y + ph.y;
        o.z = xv.z + pev.z + ph.z;
        o.w = xv.w + pev.w + ph.w;
        ((float4*)(out + off))[t] = o;
    }
}

extern "C" void kernel_launch(void* const* d_in, const int* in_sizes, int n_in,
                              void* d_out, int out_size)
{
    const float* x      = (const float*)d_in[0];
    const float* angles = (const float*)d_in[1];
    float* out          = (float*)d_out;
    (void)in_sizes; (void)n_in; (void)out_size;
    peq_kernel<<<Sk, 256>>>(x, angles, out);
}